// round 1
// baseline (speedup 1.0000x reference)
#include <cuda_runtime.h>

// Problem constants (fixed by the reference):
//   l,r: [N, C, H, W] = [2, 32, 128, 256] fp32
//   out: [N, C, D, H, W], D = 48
//   out[n,c,d,h,w] = (w >= d) ? l[n,c,h,w] - r[n,c,h,w-d] : 1.0f
#define NB   2
#define CC   32
#define HH   128
#define WW   256
#define DD   48
#define NC   (NB * CC)       // 64 fused n*C+c planes

// One block per (nc, h) row. 256 threads.
// Stage the 256-float l-row and r-row in shared memory once, then emit all
// 48 disparity rows. Warp layout: lane = tid & 63 selects the w-quad (float4),
// dgrp = tid >> 6 in [0,4) selects the disparity residue; the d-loop covers
// d = 4*i + dgrp for i in [0,12). Within a warp all threads share d and write
// a contiguous 512B burst -> perfectly coalesced STG.128.
__global__ __launch_bounds__(256) void cost_volume_kernel(
    const float* __restrict__ l,
    const float* __restrict__ r,
    float* __restrict__ out)
{
    __shared__ float ls[WW];
    __shared__ float rs[WW];

    const int row = blockIdx.x;        // 0 .. NC*HH-1
    const int nc  = row >> 7;          // row / HH
    const int h   = row & (HH - 1);    // row % HH

    const int tid = threadIdx.x;

    // Stage input rows (one float per thread, fully coalesced).
    const size_t in_base = ((size_t)nc * HH + h) * WW;
    ls[tid] = l[in_base + tid];
    rs[tid] = r[in_base + tid];
    __syncthreads();

    const int lane = tid & 63;         // w-quad index, w0 = 4*lane
    const int dgrp = tid >> 6;         // 0..3
    const int w0   = lane << 2;

    // l values don't depend on d -> hoist the float4 read out of the loop.
    const float4 lv = reinterpret_cast<const float4*>(ls)[lane];
    const float lvj[4] = { lv.x, lv.y, lv.z, lv.w };

    // Output base for this (nc, h) row at d = dgrp.
    float* orow = out + (((size_t)nc * DD + dgrp) * HH + h) * WW + w0;
    const size_t dstride = (size_t)4 * HH * WW;  // advance d by 4 each iter

    #pragma unroll
    for (int i = 0; i < DD / 4; ++i) {
        const int d = (i << 2) + dgrp;
        float4 o;
        float* oj = reinterpret_cast<float*>(&o);
        #pragma unroll
        for (int j = 0; j < 4; ++j) {
            const int w = w0 + j;
            oj[j] = (w >= d) ? (lvj[j] - rs[w - d]) : 1.0f;
        }
        *reinterpret_cast<float4*>(orow) = o;
        orow += dstride;
    }
}

extern "C" void kernel_launch(void* const* d_in, const int* in_sizes, int n_in,
                              void* d_out, int out_size)
{
    (void)in_sizes; (void)n_in; (void)out_size;
    const float* l = (const float*)d_in[0];
    const float* r = (const float*)d_in[1];
    float* out = (float*)d_out;

    dim3 grid(NC * HH);   // 8192 blocks
    dim3 block(256);
    cost_volume_kernel<<<grid, block>>>(l, r, out);
}

// round 2
// speedup vs baseline: 1.2215x; 1.2215x over previous
#include <cuda_runtime.h>

// l,r: [N, C, H, W] = [2, 32, 128, 256] fp32
// out: [N, C, D, H, W], D = 48
// out[n,c,d,h,w] = (w >= d) ? l[n,c,h,w] - r[n,c,h,w-d] : 1.0f
#define NB   2
#define CC   32
#define HH   128
#define WW   256
#define DD   48
#define NC   (NB * CC)       // 64 fused n*C+c planes
#define PAD  64              // front pad for rs (covers max negative index -48)

// Emit the 12 disparity rows d = 4*i + DG for this thread's w-quad.
// Register-rotation: window rs[w0-4i-DG .. +3] is assembled from two aligned
// float4 quads A (base w0-4i-4) and B (base w0-4i); only ONE new LDS.128 per
// iteration, previous A becomes next B.
template<int DG>
__device__ __forceinline__ void emit_rows(const float4 lv, const float* rs,
                                          const int w0, float* orow)
{
    const size_t dstride = (size_t)4 * HH * WW;   // d += 4 each iteration
    float4 B = *reinterpret_cast<const float4*>(rs + w0);
    #pragma unroll
    for (int i = 0; i < DD / 4; ++i) {
        const int d = 4 * i + DG;
        const float4 A = *reinterpret_cast<const float4*>(rs + w0 - 4 * i - 4);
        float w0v, w1v, w2v, w3v;                 // window[j] = rs[w0 - d + j]
        if      (DG == 0) { w0v = B.x; w1v = B.y; w2v = B.z; w3v = B.w; }
        else if (DG == 1) { w0v = A.w; w1v = B.x; w2v = B.y; w3v = B.z; }
        else if (DG == 2) { w0v = A.z; w1v = A.w; w2v = B.x; w3v = B.y; }
        else              { w0v = A.y; w1v = A.z; w2v = A.w; w3v = B.x; }
        float4 o;
        o.x = (w0 + 0 >= d) ? lv.x - w0v : 1.0f;
        o.y = (w0 + 1 >= d) ? lv.y - w1v : 1.0f;
        o.z = (w0 + 2 >= d) ? lv.z - w2v : 1.0f;
        o.w = (w0 + 3 >= d) ? lv.w - w3v : 1.0f;
        __stcs(reinterpret_cast<float4*>(orow), o);   // streaming store
        orow += dstride;
        B = A;
    }
}

// One block per (nc, h) row, 256 threads.
// lane = tid & 63 -> w-quad (w0 = 4*lane); dgrp = tid >> 6 -> disparity residue.
// Within each warp all threads share d: every STG.128 is a contiguous 512B burst.
__global__ __launch_bounds__(256) void cost_volume_kernel(
    const float* __restrict__ l,
    const float* __restrict__ r,
    float* __restrict__ out)
{
    __shared__ float ls[WW];
    __shared__ float rs_pad[PAD + WW];
    float* rs = rs_pad + PAD;

    const int row = blockIdx.x;        // 0 .. NC*HH-1
    const int nc  = row >> 7;          // row / HH
    const int h   = row & (HH - 1);    // row % HH
    const int tid = threadIdx.x;

    const size_t in_base = ((size_t)nc * HH + h) * WW;
    ls[tid] = l[in_base + tid];
    rs[tid] = r[in_base + tid];
    if (tid < PAD) rs_pad[tid] = 0.0f;   // masked region reads land here
    __syncthreads();

    const int lane = tid & 63;
    const int dgrp = tid >> 6;
    const int w0   = lane << 2;

    const float4 lv = reinterpret_cast<const float4*>(ls)[lane];
    float* orow = out + (((size_t)nc * DD + dgrp) * HH + h) * WW + w0;

    switch (dgrp) {                    // warp-uniform: no divergence
        case 0: emit_rows<0>(lv, rs, w0, orow); break;
        case 1: emit_rows<1>(lv, rs, w0, orow); break;
        case 2: emit_rows<2>(lv, rs, w0, orow); break;
        default: emit_rows<3>(lv, rs, w0, orow); break;
    }
}

extern "C" void kernel_launch(void* const* d_in, const int* in_sizes, int n_in,
                              void* d_out, int out_size)
{
    (void)in_sizes; (void)n_in; (void)out_size;
    const float* l = (const float*)d_in[0];
    const float* r = (const float*)d_in[1];
    float* out = (float*)d_out;

    cost_volume_kernel<<<NC * HH, 256>>>(l, r, out);
}

// round 4
// speedup vs baseline: 1.5943x; 1.3052x over previous
#include <cuda_runtime.h>

// l,r: [N, C, H, W] = [2, 32, 128, 256] fp32
// out: [N, C, D, H, W], D = 48
// out[n,c,d,h,w] = (w >= d) ? l[n,c,h,w] - r[n,c,h,w-d] : 1.0f
#define NB   2
#define CC   32
#define HH   128
#define WW   256
#define DD   48
#define NC   (NB * CC)        // 64 fused n*C+c planes
#define NROWS (NC * HH)       // 8192 total (nc,h) rows; row = nc*HH + h
#define PAD  64               // front pad (max negative window index is -48)
#define RPB  4                // rows per block (256 threads / 64 lanes)

// One block = 4 rows x 64 lanes. Each thread owns one w-quad (w0 = 4*lane)
// and emits ALL 48 disparities for it. Per iteration i the aligned quad pair
//   B = rs[w0-4i .. +3],  A = rs[w0-4i-4 .. +3]
// supplies the windows for d = 4i+0..3 via pure register selection:
//   window(d=4i+dg)[j] = rs[w0 - d + j]  ->  picks from {A,B} with shift dg.
// 13 LDS.128 + 48 STG.128 per thread; no redundant shared reads.
__global__ __launch_bounds__(256) void cost_volume_kernel(
    const float* __restrict__ l,
    const float* __restrict__ r,
    float* __restrict__ out)
{
    __shared__ float rs_s[RPB][PAD + WW];

    const int tid  = threadIdx.x;
    const int lr   = tid >> 6;            // local row 0..3
    const int lane = tid & 63;            // w-quad index
    const int row  = blockIdx.x * RPB + lr;   // 0 .. NROWS-1
    const int nc   = row >> 7;
    const int h    = row & (HH - 1);

    float* rs = &rs_s[lr][PAD];
    const size_t in_base = (size_t)row * WW;  // (nc*HH + h) * WW
    const int w0 = lane << 2;

    // Stage this row's r into shared (one LDG.128 + STS.128 per thread).
    *reinterpret_cast<float4*>(rs + w0) =
        *reinterpret_cast<const float4*>(r + in_base + w0);
    if (lane < PAD / 4)                   // zero the 64-float front pad
        reinterpret_cast<float4*>(&rs_s[lr][0])[lane] = make_float4(0.f, 0.f, 0.f, 0.f);

    // l-quad straight from gmem (no shared needed: private to this thread).
    const float4 lv = *reinterpret_cast<const float4*>(l + in_base + w0);
    __syncthreads();

    float4 B = *reinterpret_cast<const float4*>(rs + w0);

    // Output position for (nc, d=0, h, w0).
    float* obase = out + ((size_t)nc * DD * HH + h) * WW + w0;
    const size_t dstride = (size_t)HH * WW;

    #pragma unroll
    for (int i = 0; i < DD / 4; ++i) {
        const float4 A = *reinterpret_cast<const float4*>(rs + w0 - 4 * i - 4);
        const float win[8] = { A.x, A.y, A.z, A.w, B.x, B.y, B.z, B.w };
        // win[4 - dg + j] == rs[w0 - (4i+dg) + j]
        #pragma unroll
        for (int dg = 0; dg < 4; ++dg) {
            const int d = 4 * i + dg;
            float4 o;
            o.x = (w0 + 0 >= d) ? lv.x - win[4 - dg + 0] : 1.0f;
            o.y = (w0 + 1 >= d) ? lv.y - win[4 - dg + 1] : 1.0f;
            o.z = (w0 + 2 >= d) ? lv.z - win[4 - dg + 2] : 1.0f;
            o.w = (w0 + 3 >= d) ? lv.w - win[4 - dg + 3] : 1.0f;
            __stcs(reinterpret_cast<float4*>(obase + (size_t)d * dstride), o);
        }
        B = A;
    }
}

extern "C" void kernel_launch(void* const* d_in, const int* in_sizes, int n_in,
                              void* d_out, int out_size)
{
    (void)in_sizes; (void)n_in; (void)out_size;
    const float* l = (const float*)d_in[0];
    const float* r = (const float*)d_in[1];
    float* out = (float*)d_out;

    cost_volume_kernel<<<NROWS / RPB, 256>>>(l, r, out);
}